// round 1
// baseline (speedup 1.0000x reference)
#include <cuda_runtime.h>

// CIN (xDeepFM) fused 3-layer kernel, fp32, FFMA2 (fma.rn.f32x2) path.
// Shapes: X (B,32,32); W0 (1024,128); W1/W2 (4096,128); biases (128).
// out (B, 384) = per-layer sum over embedding dim d.
//
// One CTA per batch element. 64 threads. Thread (hg, dg) owns output tile
// h in [4*hg, 4*hg+4) x d in [16*dg, 16*dg+16), accumulated as 32 packed
// f32x2 registers. Per K element (k = f*fk + g):
//   - 1x LDG.128: 4 contiguous W[k, h0..h0+3]   (coalesced 512B per warp)
//   - 4x LDS.128: z[g, d0..d0+15]               (warp-broadcast, 1 wavefront each)
//   - 32x fma.rn.f32x2
// z[g][d] = x0[f][d] * state[g][d] is materialized in smem per f-chunk.
// All three layers run in one kernel; state lives in smem (no HBM intermediates).

#define F0c 32
#define Dc  32
#define Hc  128
#define NT  64

__device__ __forceinline__ unsigned long long pk2(float lo, float hi) {
    unsigned long long r;
    asm("mov.b64 %0, {%1,%2};" : "=l"(r) : "f"(lo), "f"(hi));
    return r;
}
__device__ __forceinline__ void upk2(unsigned long long v, float& lo, float& hi) {
    asm("mov.b64 {%0,%1}, %2;" : "=f"(lo), "=f"(hi) : "l"(v));
}
__device__ __forceinline__ unsigned long long fma2(unsigned long long a,
                                                   unsigned long long b,
                                                   unsigned long long c) {
    unsigned long long r;
    asm("fma.rn.f32x2 %0, %1, %2, %3;" : "=l"(r) : "l"(a), "l"(b), "l"(c));
    return r;
}
__device__ __forceinline__ unsigned long long mul2(unsigned long long a,
                                                   unsigned long long b) {
    unsigned long long r;
    asm("mul.rn.f32x2 %0, %1, %2;" : "=l"(r) : "l"(a), "l"(b));
    return r;
}

__global__ void __launch_bounds__(NT)
cin_kernel(const float* __restrict__ X,
           const float* __restrict__ W0, const float* __restrict__ W1,
           const float* __restrict__ W2,
           const float* __restrict__ Bias0, const float* __restrict__ Bias1,
           const float* __restrict__ Bias2,
           float* __restrict__ out)
{
    __shared__ __align__(16) float x0s[F0c * Dc];   // 4 KB
    __shared__ __align__(16) float st[Hc * Dc];     // 16 KB (state, in-place per layer)
    __shared__ __align__(16) float zs[Hc * Dc];     // 16 KB (z chunk for current f)
    __shared__ float osum[2][Hc];                   // 1 KB (d-group partial sums)

    const int b  = blockIdx.x;
    const int t  = threadIdx.x;
    const int hg = t & 31;        // 32 h-groups of 4
    const int dg = t >> 5;        // 2 d-groups of 16
    const int h0 = hg << 2;
    const int d0 = dg << 4;

    // Load x0 (and initialize state = x0 for layer 0)
    {
        const float4* Xv = (const float4*)(X + (size_t)b * (F0c * Dc));
        float4* x0v = (float4*)x0s;
        float4* stv = (float4*)st;
        #pragma unroll
        for (int i = t; i < F0c * Dc / 4; i += NT) {
            float4 v = Xv[i];
            x0v[i] = v;
            stv[i] = v;
        }
    }

    float* outb = out + (size_t)b * (3 * Hc);

    for (int layer = 0; layer < 3; ++layer) {
        const int fk = (layer == 0) ? F0c : Hc;
        const float* W  = (layer == 0) ? W0 : ((layer == 1) ? W1 : W2);
        const float* Bv = (layer == 0) ? Bias0 : ((layer == 1) ? Bias1 : Bias2);

        unsigned long long acc[4][8];
        #pragma unroll
        for (int j = 0; j < 4; ++j)
            #pragma unroll
            for (int i = 0; i < 8; ++i) acc[j][i] = 0ull;

        for (int f = 0; f < F0c; ++f) {
            __syncthreads();   // zs safe to overwrite (prev f's readers done);
                               // also orders state/x0 writes before first read

            // Build z[g][d] = x0[f][d] * state[g][d] cooperatively (f32x2 muls)
            {
                const unsigned long long* x0r =
                    (const unsigned long long*)(x0s + f * Dc);
                const ulonglong2* sv2 = (const ulonglong2*)st;
                ulonglong2* zv = (ulonglong2*)zs;
                const int n4 = fk * Dc / 4;     // float4 count
                for (int i = t; i < n4; i += NT) {
                    int dq = i & 7;             // quad within 32-float row
                    unsigned long long xlo = x0r[dq * 2];
                    unsigned long long xhi = x0r[dq * 2 + 1];
                    ulonglong2 sv = sv2[i];
                    ulonglong2 r;
                    r.x = mul2(xlo, sv.x);
                    r.y = mul2(xhi, sv.y);
                    zv[i] = r;
                }
            }
            __syncthreads();

            const float4* Wr = (const float4*)W + (size_t)f * fk * (Hc / 4) + hg;
            #pragma unroll 4
            for (int g = 0; g < fk; ++g) {
                const float4 w = __ldg(Wr + (size_t)g * (Hc / 4));
                unsigned long long wp0 = pk2(w.x, w.x);
                unsigned long long wp1 = pk2(w.y, w.y);
                unsigned long long wp2 = pk2(w.z, w.z);
                unsigned long long wp3 = pk2(w.w, w.w);
                const ulonglong2* zr = (const ulonglong2*)(zs + g * Dc + d0);
                ulonglong2 p0 = zr[0], p1 = zr[1], p2 = zr[2], p3 = zr[3];
                unsigned long long zq[8] =
                    {p0.x, p0.y, p1.x, p1.y, p2.x, p2.y, p3.x, p3.y};
                #pragma unroll
                for (int i = 0; i < 8; ++i) {
                    acc[0][i] = fma2(wp0, zq[i], acc[0][i]);
                    acc[1][i] = fma2(wp1, zq[i], acc[1][i]);
                    acc[2][i] = fma2(wp2, zq[i], acc[2][i]);
                    acc[3][i] = fma2(wp3, zq[i], acc[3][i]);
                }
            }
        }
        __syncthreads();   // all K-loop reads complete before state overwrite

        // Epilogue: bias, write new state, partial d-sums
        const float4 bq = ((const float4*)Bv)[hg];
        const float bj[4] = {bq.x, bq.y, bq.z, bq.w};
        #pragma unroll
        for (int j = 0; j < 4; ++j) {
            float s = 0.f;
            float* strow = st + (h0 + j) * Dc + d0;
            #pragma unroll
            for (int i = 0; i < 8; ++i) {
                float lo, hi;
                upk2(acc[j][i], lo, hi);
                lo += bj[j];
                hi += bj[j];
                strow[2 * i]     = lo;
                strow[2 * i + 1] = hi;
                s += lo + hi;
            }
            osum[dg][h0 + j] = s;
        }
        __syncthreads();
        if (dg == 0) {
            float4 o;
            o.x = osum[0][h0 + 0] + osum[1][h0 + 0];
            o.y = osum[0][h0 + 1] + osum[1][h0 + 1];
            o.z = osum[0][h0 + 2] + osum[1][h0 + 2];
            o.w = osum[0][h0 + 3] + osum[1][h0 + 3];
            ((float4*)(outb + layer * Hc))[hg] = o;
        }
    }
}

extern "C" void kernel_launch(void* const* d_in, const int* in_sizes, int n_in,
                              void* d_out, int out_size) {
    const float* X  = (const float*)d_in[0];
    const float* W0 = (const float*)d_in[1];
    const float* W1 = (const float*)d_in[2];
    const float* W2 = (const float*)d_in[3];
    const float* B0 = (const float*)d_in[4];
    const float* B1 = (const float*)d_in[5];
    const float* B2 = (const float*)d_in[6];
    float* out = (float*)d_out;

    const int B = in_sizes[0] / (F0c * Dc);
    cin_kernel<<<B, NT>>>(X, W0, W1, W2, B0, B1, B2, out);
}